// round 6
// baseline (speedup 1.0000x reference)
#include <cuda_runtime.h>
#include <cuda_bf16.h>
#include <math.h>
#include <stdint.h>

// Problem constants
#define BB 512
#define KK 256
#define NN 512
#define CC 6
#define CHUNK 128            // tracks per track-block
#define TPB 128              // threads per block
#define NLAM 64              // lam blocks (8 batches each)
#define MAXTB 2048           // max track blocks = 512 * ceil(512/128)
#define GRID (NLAM + MAXTB)  // 2112

#define LOG2E_F 1.4426950408889634f
#define LN2_F   0.6931471805599453f
#define LOG2PI_LOG2E 2.6514961294723187  // log2(2*pi)

// ---------------- scratch (static device globals; no allocation) -------------
__device__ double4 g_part[GRID];     // {spatial, efs, cnt, 0} per block
__device__ double  g_lam[BB];
__device__ int     g_count[BB];
__device__ int     g_map[MAXTB];     // packed (b<<2)|chunk
__device__ int     g_total;
__device__ unsigned int g_done = 0;

// ---------------- fast math helpers ------------------------------------------
__device__ __forceinline__ float ex2f(float x) {
    float y; asm("ex2.approx.ftz.f32 %0, %1;" : "=f"(y) : "f"(x)); return y;
}
__device__ __forceinline__ float lg2f(float x) {
    float y; asm("lg2.approx.ftz.f32 %0, %1;" : "=f"(y) : "f"(x)); return y;
}
__device__ __forceinline__ double warpRedD(double v) {
    #pragma unroll
    for (int o = 16; o; o >>= 1) v += __shfl_down_sync(0xffffffffu, v, o);
    return v;
}

// ---------------- kernel A: scheduler -----------------------------------------
__global__ __launch_bounds__(512) void sched_kernel(const uint32_t* __restrict__ mask) {
    const int b = threadIdx.x;
    const uint32_t* mb = mask + (size_t)b * NN;

    // prefix-mask count via 3 rounds of parallel probes
    int s1 = 0;
    #pragma unroll
    for (int m = 1; m <= 8; m++) s1 += (mb[64 * m - 1] != 0u);
    int cnt;
    if (s1 == 8) {
        cnt = 512;
    } else {
        const int base1 = 64 * s1;
        int s2 = 0;
        #pragma unroll
        for (int m = 1; m <= 7; m++) s2 += (mb[base1 + 8 * m - 1] != 0u);
        const int base2 = base1 + 8 * s2;
        int s3 = 0;
        #pragma unroll
        for (int o = 0; o < 7; o++) s3 += (mb[base2 + o] != 0u);
        cnt = base2 + s3;
    }

    const int nb = (cnt + CHUNK - 1) / CHUNK;   // 0..4

    // exclusive scan over 512 values (Hillis-Steele)
    __shared__ int sv[512];
    sv[b] = nb;
    __syncthreads();
    for (int off = 1; off < 512; off <<= 1) {
        int v = sv[b];
        int add = (b >= off) ? sv[b - off] : 0;
        __syncthreads();
        sv[b] = v + add;
        __syncthreads();
    }
    const int incl = sv[b];
    const int excl = incl - nb;

    g_count[b] = cnt;
    for (int l = 0; l < nb; l++) g_map[excl + l] = (b << 2) | l;
    if (b == 511) g_total = incl;
}

// ---------------- kernel B: main (lam blocks + track blocks + finalize) -------
__global__ __launch_bounds__(TPB) void main_kernel(
    const float* __restrict__ pi,
    const float* __restrict__ mu,
    const float* __restrict__ L,
    const float* __restrict__ ef_logits,
    const float* __restrict__ tracks,
    float* __restrict__ out)
{
    const int j   = blockIdx.x;
    const int tid = threadIdx.x;
    const int wid = tid >> 5, lid = tid & 31;

    __shared__ float4 scf4[KK];        // {c0,c1,c2,c3}  4 KB
    __shared__ float2 scf2[KK];        // {c4,c5}        2 KB
    __shared__ float  sce[KK * CC];    // ce[k*6+g]      6 KB
    __shared__ double red[4 * 3];
    __shared__ bool   isLast;

    if (j < NLAM) {
        // ---- lam blocks: warp w handles batches j*8 + 2w, +2w+1 ----
        #pragma unroll
        for (int u = 0; u < 2; u++) {
            const int b = j * 8 + wid * 2 + u;
            const float* pb = pi + (size_t)b * KK;
            double lam = 0.0;
            #pragma unroll
            for (int o = 0; o < KK; o += 32) lam += (double)pb[o + lid];
            lam = warpRedD(lam);
            if (lid == 0) g_lam[b] = lam;
        }
        if (tid == 0) g_part[j] = make_double4(0.0, 0.0, 0.0, 0.0);
    } else {
        const int j2 = j - NLAM;
        double spatial = 0.0, efs = 0.0, cntp = 0.0;

        if (j2 < g_total) {
            const int mp   = g_map[j2];
            const int b    = mp >> 2;
            const int n0   = (mp & 3) * CHUNK;
            const int cntb = g_count[b];

            // ---- staging: thread tid builds coefficients for k = tid, tid+128 ----
            #pragma unroll
            for (int kk = 0; kk < 2; kk++) {
                const int k = tid + kk * TPB;
                const int i = b * KK + k;
                double pv = (double)pi[i];
                double a  = (double)L[i * 4 + 0];
                double bb = (double)L[i * 4 + 2];
                double c  = (double)L[i * 4 + 3];
                double m0 = (double)mu[i * 2 + 0];
                double m1 = (double)mu[i * 2 + 1];

                double base2 = log2(pv) - LOG2PI_LOG2E - log2(a * c);  // < 0

                const double RQ2 = 0.72134752044448170;  // 0.5 * log2(e)
                double A2  = RQ2 / (a * a);
                double Cr2 = RQ2 / (c * c);
                double BA  = bb / a;
                double P = A2 + Cr2 * BA * BA;
                double Q = Cr2;
                double R = -2.0 * Cr2 * BA;

                float4 v4;
                float2 v2;
                v4.x = (float)(base2 - P * m0 * m0 - Q * m1 * m1 - R * m0 * m1);
                v4.y = (float)(2.0 * P * m0 + R * m1);
                v4.z = (float)(2.0 * Q * m1 + R * m0);
                v4.w = (float)(-P);
                v2.x = (float)(-Q);
                v2.y = (float)(-R);
                scf4[k] = v4;
                scf2[k] = v2;

                // CE table: lse(ef_logits) - ef_logits[c]
                float e[CC];
                float mx = -INFINITY;
                #pragma unroll
                for (int c2 = 0; c2 < CC; c2++) {
                    e[c2] = ef_logits[(size_t)i * CC + c2];
                    mx = fmaxf(mx, e[c2]);
                }
                float ssum = 0.f;
                #pragma unroll
                for (int c2 = 0; c2 < CC; c2++) ssum += ex2f((e[c2] - mx) * LOG2E_F);
                float lse = mx + lg2f(ssum) * LN2_F;
                #pragma unroll
                for (int c2 = 0; c2 < CC; c2++) sce[k * CC + c2] = lse - e[c2];
            }
            __syncthreads();

            // ---- per-track pass: thread tid owns track n0 + tid ----
            const int n = n0 + tid;
            const bool act = (n < cntb);
            if (__ballot_sync(0xffffffffu, act) != 0u) {
                // tracks memory is valid (finite) even past count
                const float* tr = tracks + ((size_t)b * NN + n) * 6;
                const float x0 = tr[0], x1 = tr[1];
                const int   g  = (int)tr[5];
                const float xx0 = x0 * x0, xx1 = x1 * x1, x01 = x0 * x1;

                float s = 0.f, t = 0.f;
                #pragma unroll 8
                for (int k = 0; k < KK; k++) {
                    float4 c4 = scf4[k];
                    float2 c2 = scf2[k];
                    float q = fmaf(c4.y, x0, c4.x);
                    q = fmaf(c4.z, x1, q);
                    q = fmaf(c4.w, xx0, q);
                    q = fmaf(c2.x, xx1, q);
                    q = fmaf(c2.y, x01, q);
                    float p = ex2f(q);
                    s += p;
                    t = fmaf(p, sce[k * CC + g], t);
                }
                if (act) {
                    spatial = -(double)(lg2f(s) * LN2_F);
                    efs     = (double)(t / s);
                    cntp    = 1.0;
                }
            }
        }

        // ---- block reduce 3 doubles (uniform control, 4 warps) ----
        spatial = warpRedD(spatial);
        efs     = warpRedD(efs);
        cntp    = warpRedD(cntp);
        if (lid == 0) {
            red[wid]     = spatial;
            red[4 + wid] = efs;
            red[8 + wid] = cntp;
        }
        __syncthreads();
        if (tid == 0) {
            double s0 = 0, s1 = 0, s2 = 0;
            #pragma unroll
            for (int w = 0; w < 4; w++) {
                s0 += red[w]; s1 += red[4 + w]; s2 += red[8 + w];
            }
            g_part[j] = make_double4(s0, s1, s2, 0.0);
        }
    }

    // ---- last-block-done finalize (deterministic fixed-order sums) ----
    __threadfence();
    if (tid == 0) {
        unsigned int v = atomicAdd(&g_done, 1u);
        isLast = (v == (unsigned)GRID - 1u);
    }
    __syncthreads();
    if (isLast) {
        double spSum = 0, efSum = 0, cntSum = 0;
        for (int q = tid; q < GRID; q += TPB) {
            double4 e = g_part[q];
            spSum  += e.x;
            efSum  += e.y;
            cntSum += e.z;
        }
        double lamSum = 0, l1Sum = 0;
        for (int b2 = tid; b2 < BB; b2 += TPB) {
            double lm = g_lam[b2];
            double gc = (double)g_count[b2];
            lamSum += lm;
            l1Sum  += fabs(lm - gc) * sqrt(gc + 1.0);
        }
        spSum  = warpRedD(spSum);
        efSum  = warpRedD(efSum);
        cntSum = warpRedD(cntSum);
        lamSum = warpRedD(lamSum);
        l1Sum  = warpRedD(l1Sum);
        __syncthreads();
        __shared__ double red5[4 * 5];
        if (lid == 0) {
            red5[wid]      = spSum;
            red5[4 + wid]  = efSum;
            red5[8 + wid]  = cntSum;
            red5[12 + wid] = lamSum;
            red5[16 + wid] = l1Sum;
        }
        __syncthreads();
        if (tid == 0) {
            double a0 = 0, a1 = 0, a2 = 0, a3 = 0, a4 = 0;
            #pragma unroll
            for (int w = 0; w < 4; w++) {
                a0 += red5[w]; a1 += red5[4 + w]; a2 += red5[8 + w];
                a3 += red5[12 + w]; a4 += red5[16 + w];
            }
            double n_total    = a2 > 1.0 ? a2 : 1.0;
            double spatialL   = a0 / n_total;
            double efL        = a1 / n_total;
            double count_loss = a3 / (double)BB;
            double count_l1   = a4 / (double)BB;
            double total = count_loss + spatialL + efL + count_l1;
            out[0] = (float)total;
            out[1] = (float)spatialL;
            out[2] = (float)count_loss;
            out[3] = (float)count_l1;
            out[4] = (float)efL;
            g_done = 0;  // reset for next graph replay
        }
    }
}

// ---------------- launch -------------------------------------------------------
extern "C" void kernel_launch(void* const* d_in, const int* in_sizes, int n_in,
                              void* d_out, int out_size) {
    const float* pi        = (const float*)d_in[0];
    const float* mu        = (const float*)d_in[1];
    const float* L         = (const float*)d_in[2];
    const float* ef_logits = (const float*)d_in[3];
    const float* tracks    = (const float*)d_in[4];
    const uint32_t* mask   = (const uint32_t*)d_in[5];

    sched_kernel<<<1, 512>>>(mask);
    main_kernel<<<GRID, TPB>>>(pi, mu, L, ef_logits, tracks, (float*)d_out);
}

// round 7
// speedup vs baseline: 1.2299x; 1.2299x over previous
#include <cuda_runtime.h>
#include <cuda_bf16.h>
#include <math.h>
#include <stdint.h>

// Problem constants
#define BB 512
#define KK 256
#define NN 512
#define CC 6
#define HALF_N 256      // tracks per block (2 blocks per batch)
#define TPB 128         // threads per block; each thread owns 2 tracks

#define LOG2E_F 1.4426950408889634f
#define LN2_F   0.6931471805599453f
#define LOG2PI_LOG2E_F 2.6514961294723187f  // log2(2*pi)
#define RQ2_F 0.72134752044448170f          // 0.5 * log2(e)

// ---------------- scratch (static device globals; no allocation) -------------
__device__ double4 g_part[2 * BB];           // {spatial, efs, cnt, lam} per block
__device__ unsigned int g_done = 0;

// ---------------- fast math helpers ------------------------------------------
__device__ __forceinline__ float ex2f(float x) {
    float y; asm("ex2.approx.ftz.f32 %0, %1;" : "=f"(y) : "f"(x)); return y;
}
__device__ __forceinline__ float lg2f(float x) {
    float y; asm("lg2.approx.ftz.f32 %0, %1;" : "=f"(y) : "f"(x)); return y;
}
__device__ __forceinline__ double warpRedD(double v) {
    #pragma unroll
    for (int o = 16; o; o >>= 1) v += __shfl_down_sync(0xffffffffu, v, o);
    return v;
}

// ---------------- main kernel (fully fused) -----------------------------------
__global__ __launch_bounds__(TPB, 12) void main_kernel(
    const float* __restrict__ pi,
    const float* __restrict__ mu,
    const float* __restrict__ L,
    const float* __restrict__ ef_logits,
    const float* __restrict__ tracks,
    const uint32_t* __restrict__ mask,
    float* __restrict__ out)
{
    const int bid  = blockIdx.x;
    const int b    = bid >> 1;
    const int half = bid & 1;
    const int tid  = threadIdx.x;

    __shared__ float4 scf4[KK];        // {c0,c1,c2,c3}  4 KB
    __shared__ float2 scf2[KK];        // {c4,c5}        2 KB
    __shared__ float  sce[KK * CC];    // ce[k*6+g]      6 KB
    __shared__ double red[4 * 4];
    __shared__ bool   isLast;

    // Lambda contribution: only half 0 accumulates pi (each thread covers 2 k's)
    double lam = 0.0;
    if (half == 0) {
        lam = (double)pi[(size_t)b * KK + tid] + (double)pi[(size_t)b * KK + tid + TPB];
    }

    const int n0 = half * HALF_N;
    // prefix-mask property: first inactive => whole 256-track range inactive
    const bool blockActive = (mask[(size_t)b * NN + n0] != 0u);

    double spatial = 0.0, efs = 0.0, cnt = 0.0;

    if (blockActive) {
        // ---- staging (float): thread tid builds coefficients for k=tid, tid+128 ----
        #pragma unroll
        for (int kk = 0; kk < 2; kk++) {
            const int k = tid + kk * TPB;
            const int i = b * KK + k;
            float pv = pi[i];
            float a  = L[i * 4 + 0];
            float bb = L[i * 4 + 2];
            float c  = L[i * 4 + 3];
            float m0 = mu[i * 2 + 0];
            float m1 = mu[i * 2 + 1];

            float base2 = lg2f(pv) - LOG2PI_LOG2E_F - lg2f(a * c);  // < 0

            float A2  = RQ2_F / (a * a);
            float Cr2 = RQ2_F / (c * c);
            float BA  = bb / a;
            float P = fmaf(Cr2 * BA, BA, A2);
            float Q = Cr2;
            float R = -2.0f * Cr2 * BA;

            float4 v4;
            float2 v2;
            v4.x = base2 - P * m0 * m0 - Q * m1 * m1 - R * m0 * m1;
            v4.y = fmaf(2.0f * P, m0, R * m1);
            v4.z = fmaf(2.0f * Q, m1, R * m0);
            v4.w = -P;
            v2.x = -Q;
            v2.y = -R;
            scf4[k] = v4;
            scf2[k] = v2;

            // CE table: lse(ef_logits) - ef_logits[c]
            float e[CC];
            float mx = -INFINITY;
            #pragma unroll
            for (int c2 = 0; c2 < CC; c2++) {
                e[c2] = ef_logits[(size_t)i * CC + c2];
                mx = fmaxf(mx, e[c2]);
            }
            float ssum = 0.f;
            #pragma unroll
            for (int c2 = 0; c2 < CC; c2++) ssum += ex2f((e[c2] - mx) * LOG2E_F);
            float lse = mx + lg2f(ssum) * LN2_F;
            #pragma unroll
            for (int c2 = 0; c2 < CC; c2++) sce[k * CC + c2] = lse - e[c2];
        }
        __syncthreads();

        // ---- per-track pass: thread owns tracks n0+tid (A) and n0+tid+128 (B) ----
        const int nA = n0 + tid;
        const int nB = nA + TPB;
        const bool actA = (mask[(size_t)b * NN + nA] != 0u);
        const bool actB = (mask[(size_t)b * NN + nB] != 0u);
        const bool anyA = (__ballot_sync(0xffffffffu, actA) != 0u);
        const bool anyB = (__ballot_sync(0xffffffffu, actB) != 0u);

        if (anyA) {
            const float* trA = tracks + ((size_t)b * NN + nA) * 6;
            const float* trB = tracks + ((size_t)b * NN + nB) * 6;
            float x0A = trA[0], x1A = trA[1];
            int   gA  = (int)trA[5];
            float xx0A = x0A * x0A, xx1A = x1A * x1A, x01A = x0A * x1A;
            const float* cepA = sce + gA;

            float sA = 0.f, tA = 0.f;

            if (anyB) {
                float x0B = trB[0], x1B = trB[1];
                int   gB  = (int)trB[5];
                float xx0B = x0B * x0B, xx1B = x1B * x1B, x01B = x0B * x1B;
                const float* cepB = sce + gB;
                float sB = 0.f, tB = 0.f;

                #pragma unroll 4
                for (int k = 0; k < KK; k++) {
                    float4 c4 = scf4[k];
                    float2 c2 = scf2[k];
                    float qA = fmaf(c4.y, x0A, c4.x);
                    float qB = fmaf(c4.y, x0B, c4.x);
                    qA = fmaf(c4.z, x1A, qA);
                    qB = fmaf(c4.z, x1B, qB);
                    qA = fmaf(c4.w, xx0A, qA);
                    qB = fmaf(c4.w, xx0B, qB);
                    qA = fmaf(c2.x, xx1A, qA);
                    qB = fmaf(c2.x, xx1B, qB);
                    qA = fmaf(c2.y, x01A, qA);
                    qB = fmaf(c2.y, x01B, qB);
                    float pA = ex2f(qA);
                    float pB = ex2f(qB);
                    sA += pA;
                    sB += pB;
                    tA = fmaf(pA, cepA[k * CC], tA);
                    tB = fmaf(pB, cepB[k * CC], tB);
                }
                if (actB) {
                    spatial -= (double)(lg2f(sB) * LN2_F);
                    efs     += (double)(tB / sB);
                    cnt     += 1.0;
                }
            } else {
                #pragma unroll 8
                for (int k = 0; k < KK; k++) {
                    float4 c4 = scf4[k];
                    float2 c2 = scf2[k];
                    float qA = fmaf(c4.y, x0A, c4.x);
                    qA = fmaf(c4.z, x1A, qA);
                    qA = fmaf(c4.w, xx0A, qA);
                    qA = fmaf(c2.x, xx1A, qA);
                    qA = fmaf(c2.y, x01A, qA);
                    float pA = ex2f(qA);
                    sA += pA;
                    tA = fmaf(pA, cepA[k * CC], tA);
                }
            }
            if (actA) {
                spatial -= (double)(lg2f(sA) * LN2_F);
                efs     += (double)(tA / sA);
                cnt     += 1.0;
            }
        }
    }

    // ---- block reduce 4 doubles (uniform control, 4 warps) ----
    spatial = warpRedD(spatial);
    efs     = warpRedD(efs);
    cnt     = warpRedD(cnt);
    lam     = warpRedD(lam);
    const int wid = tid >> 5, lid = tid & 31;
    if (lid == 0) {
        red[wid]      = spatial;
        red[4 + wid]  = efs;
        red[8 + wid]  = cnt;
        red[12 + wid] = lam;
    }
    __syncthreads();
    if (tid == 0) {
        double s0 = 0, s1 = 0, s2 = 0, s3 = 0;
        #pragma unroll
        for (int w = 0; w < 4; w++) {
            s0 += red[w]; s1 += red[4 + w]; s2 += red[8 + w]; s3 += red[12 + w];
        }
        g_part[bid] = make_double4(s0, s1, s2, s3);
    }

    // ---- last-block-done finalize (deterministic fixed-order sum) ----
    __threadfence();
    if (tid == 0) {
        unsigned int v = atomicAdd(&g_done, 1u);
        isLast = (v == 2u * BB - 1u);
    }
    __syncthreads();
    if (isLast) {
        double lamSum = 0, cntSum = 0, l1Sum = 0, spSum = 0, efSum = 0;
        for (int b2 = tid; b2 < BB; b2 += TPB) {
            double4 e0 = g_part[2 * b2];
            double4 e1 = g_part[2 * b2 + 1];
            double sp = e0.x + e1.x;
            double ef = e0.y + e1.y;
            double gc = e0.z + e1.z;
            double lm = e0.w + e1.w;
            lamSum += lm;
            cntSum += gc;
            l1Sum  += fabs(lm - gc) * sqrt(gc + 1.0);
            spSum  += sp;
            efSum  += ef;
        }
        lamSum = warpRedD(lamSum);
        cntSum = warpRedD(cntSum);
        l1Sum  = warpRedD(l1Sum);
        spSum  = warpRedD(spSum);
        efSum  = warpRedD(efSum);
        __syncthreads();
        __shared__ double red5[4 * 5];
        if (lid == 0) {
            red5[wid]      = lamSum;
            red5[4 + wid]  = cntSum;
            red5[8 + wid]  = l1Sum;
            red5[12 + wid] = spSum;
            red5[16 + wid] = efSum;
        }
        __syncthreads();
        if (tid == 0) {
            double a0 = 0, a1 = 0, a2 = 0, a3 = 0, a4 = 0;
            #pragma unroll
            for (int w = 0; w < 4; w++) {
                a0 += red5[w]; a1 += red5[4 + w]; a2 += red5[8 + w];
                a3 += red5[12 + w]; a4 += red5[16 + w];
            }
            double count_loss = a0 / (double)BB;
            double n_total    = a1 > 1.0 ? a1 : 1.0;
            double count_l1   = a2 / (double)BB;
            double spatialL   = a3 / n_total;
            double efL        = a4 / n_total;
            double total = count_loss + spatialL + efL + count_l1;
            out[0] = (float)total;
            out[1] = (float)spatialL;
            out[2] = (float)count_loss;
            out[3] = (float)count_l1;
            out[4] = (float)efL;
            g_done = 0;  // reset for next graph replay
        }
    }
}

// ---------------- launch -------------------------------------------------------
extern "C" void kernel_launch(void* const* d_in, const int* in_sizes, int n_in,
                              void* d_out, int out_size) {
    const float* pi        = (const float*)d_in[0];
    const float* mu        = (const float*)d_in[1];
    const float* L         = (const float*)d_in[2];
    const float* ef_logits = (const float*)d_in[3];
    const float* tracks    = (const float*)d_in[4];
    const uint32_t* mask   = (const uint32_t*)d_in[5];

    main_kernel<<<2 * BB, TPB>>>(pi, mu, L, ef_logits, tracks, mask, (float*)d_out);
}

// round 8
// speedup vs baseline: 1.2331x; 1.0026x over previous
#include <cuda_runtime.h>
#include <cuda_bf16.h>
#include <math.h>
#include <stdint.h>

// Problem constants
#define BB 512
#define KK 256
#define NN 512
#define CC 6
#define JP (KK/2)       // 128 k-pairs
#define HALF_N 256      // tracks per block (2 blocks per batch)
#define TPB 128         // threads per block; each thread owns 2 tracks

#define LOG2E_F 1.4426950408889634f
#define LN2_F   0.6931471805599453f
#define LOG2PI_LOG2E_F 2.6514961294723187f  // log2(2*pi)
#define RQ2_F 0.72134752044448170f          // 0.5 * log2(e)

// ---------------- scratch (static device globals; no allocation) -------------
__device__ double4 g_part[2 * BB];           // {spatial, efs, cnt, lam} per block
__device__ unsigned int g_done = 0;

// ---------------- fast math helpers ------------------------------------------
__device__ __forceinline__ float ex2f(float x) {
    float y; asm("ex2.approx.ftz.f32 %0, %1;" : "=f"(y) : "f"(x)); return y;
}
__device__ __forceinline__ float lg2f(float x) {
    float y; asm("lg2.approx.ftz.f32 %0, %1;" : "=f"(y) : "f"(x)); return y;
}
__device__ __forceinline__ double warpRedD(double v) {
    #pragma unroll
    for (int o = 16; o; o >>= 1) v += __shfl_down_sync(0xffffffffu, v, o);
    return v;
}

// ---------------- main kernel (fully fused) -----------------------------------
__global__ __launch_bounds__(TPB, 12) void main_kernel(
    const float* __restrict__ pi,
    const float* __restrict__ mu,
    const float* __restrict__ L,
    const float* __restrict__ ef_logits,
    const float* __restrict__ tracks,
    const uint32_t* __restrict__ mask,
    float* __restrict__ out)
{
    const int bid  = blockIdx.x;
    const int b    = bid >> 1;
    const int half = bid & 1;
    const int tid  = threadIdx.x;

    __shared__ float4 scA[KK];         // {c0,c1,c2,c3} per k          4 KB
    __shared__ float4 scB[JP];         // {c4_k0,c5_k0,c4_k1,c5_k1}    2 KB
    __shared__ float2 sce2[JP * CC];   // {ce(2j,g), ce(2j+1,g)}       6 KB
    __shared__ double red[4 * 4];
    __shared__ bool   isLast;

    // Lambda contribution: only half 0 accumulates pi (each thread covers 2 k's)
    double lam = 0.0;
    if (half == 0) {
        lam = (double)pi[(size_t)b * KK + tid] + (double)pi[(size_t)b * KK + tid + TPB];
    }

    const int n0 = half * HALF_N;
    // prefix-mask property: first inactive => whole 256-track range inactive
    const bool blockActive = (mask[(size_t)b * NN + n0] != 0u);

    double spatial = 0.0, efs = 0.0, cnt = 0.0;

    if (blockActive) {
        // ---- staging (float): thread tid builds coefficients for k=tid, tid+128 ----
        #pragma unroll
        for (int kk = 0; kk < 2; kk++) {
            const int k = tid + kk * TPB;
            const int i = b * KK + k;
            float pv = pi[i];
            float a  = L[i * 4 + 0];
            float bb = L[i * 4 + 2];
            float c  = L[i * 4 + 3];
            float m0 = mu[i * 2 + 0];
            float m1 = mu[i * 2 + 1];

            float base2 = lg2f(pv) - LOG2PI_LOG2E_F - lg2f(a * c);  // < 0

            float A2  = RQ2_F / (a * a);
            float Cr2 = RQ2_F / (c * c);
            float BA  = bb / a;
            float P = fmaf(Cr2 * BA, BA, A2);
            float Q = Cr2;
            float R = -2.0f * Cr2 * BA;

            float4 v4;
            v4.x = base2 - P * m0 * m0 - Q * m1 * m1 - R * m0 * m1;
            v4.y = fmaf(2.0f * P, m0, R * m1);
            v4.z = fmaf(2.0f * Q, m1, R * m0);
            v4.w = -P;
            scA[k] = v4;

            const int j = k >> 1, lane = k & 1;
            float* fB = (float*)scB;
            fB[j * 4 + lane * 2 + 0] = -Q;
            fB[j * 4 + lane * 2 + 1] = -R;

            // CE table: lse(ef_logits) - ef_logits[c], paired layout
            float e[CC];
            float mx = -INFINITY;
            #pragma unroll
            for (int c2 = 0; c2 < CC; c2++) {
                e[c2] = ef_logits[(size_t)i * CC + c2];
                mx = fmaxf(mx, e[c2]);
            }
            float ssum = 0.f;
            #pragma unroll
            for (int c2 = 0; c2 < CC; c2++) ssum += ex2f((e[c2] - mx) * LOG2E_F);
            float lse = mx + lg2f(ssum) * LN2_F;
            float* fce = (float*)sce2;
            #pragma unroll
            for (int c2 = 0; c2 < CC; c2++) fce[(j * CC + c2) * 2 + lane] = lse - e[c2];
        }
        __syncthreads();

        // ---- per-track pass: thread owns tracks n0+tid (A) and n0+tid+128 (B) ----
        const int nA = n0 + tid;
        const int nB = nA + TPB;
        const bool actA = (mask[(size_t)b * NN + nA] != 0u);
        const bool actB = (mask[(size_t)b * NN + nB] != 0u);
        const bool anyA = (__ballot_sync(0xffffffffu, actA) != 0u);
        const bool anyB = (__ballot_sync(0xffffffffu, actB) != 0u);

        if (anyA) {
            const float* trA = tracks + ((size_t)b * NN + nA) * 6;
            const float* trB = tracks + ((size_t)b * NN + nB) * 6;
            float x0A = trA[0], x1A = trA[1];
            int   gA  = (int)trA[5];
            float xx0A = x0A * x0A, xx1A = x1A * x1A, x01A = x0A * x1A;
            const float2* cepA = sce2 + gA;

            float sA = 0.f, tA = 0.f;

            if (anyB) {
                float x0B = trB[0], x1B = trB[1];
                int   gB  = (int)trB[5];
                float xx0B = x0B * x0B, xx1B = x1B * x1B, x01B = x0B * x1B;
                const float2* cepB = sce2 + gB;
                float sB = 0.f, tB = 0.f;

                #pragma unroll 4
                for (int j = 0; j < JP; j++) {
                    float4 a0 = scA[2 * j];
                    float4 a1 = scA[2 * j + 1];
                    float4 bbq = scB[j];
                    float2 ceA = cepA[j * CC];
                    float2 ceB = cepB[j * CC];

                    float qA0 = fmaf(a0.y, x0A, a0.x);
                    float qB0 = fmaf(a0.y, x0B, a0.x);
                    float qA1 = fmaf(a1.y, x0A, a1.x);
                    float qB1 = fmaf(a1.y, x0B, a1.x);
                    qA0 = fmaf(a0.z, x1A, qA0);
                    qB0 = fmaf(a0.z, x1B, qB0);
                    qA1 = fmaf(a1.z, x1A, qA1);
                    qB1 = fmaf(a1.z, x1B, qB1);
                    qA0 = fmaf(a0.w, xx0A, qA0);
                    qB0 = fmaf(a0.w, xx0B, qB0);
                    qA1 = fmaf(a1.w, xx0A, qA1);
                    qB1 = fmaf(a1.w, xx0B, qB1);
                    qA0 = fmaf(bbq.x, xx1A, qA0);
                    qB0 = fmaf(bbq.x, xx1B, qB0);
                    qA1 = fmaf(bbq.z, xx1A, qA1);
                    qB1 = fmaf(bbq.z, xx1B, qB1);
                    qA0 = fmaf(bbq.y, x01A, qA0);
                    qB0 = fmaf(bbq.y, x01B, qB0);
                    qA1 = fmaf(bbq.w, x01A, qA1);
                    qB1 = fmaf(bbq.w, x01B, qB1);

                    float pA0 = ex2f(qA0);
                    float pB0 = ex2f(qB0);
                    float pA1 = ex2f(qA1);
                    float pB1 = ex2f(qB1);

                    sA += pA0;
                    sB += pB0;
                    sA += pA1;
                    sB += pB1;
                    tA = fmaf(pA0, ceA.x, tA);
                    tB = fmaf(pB0, ceB.x, tB);
                    tA = fmaf(pA1, ceA.y, tA);
                    tB = fmaf(pB1, ceB.y, tB);
                }
                if (actB) {
                    spatial -= (double)(lg2f(sB) * LN2_F);
                    efs     += (double)(tB / sB);
                    cnt     += 1.0;
                }
            } else {
                #pragma unroll 4
                for (int j = 0; j < JP; j++) {
                    float4 a0 = scA[2 * j];
                    float4 a1 = scA[2 * j + 1];
                    float4 bbq = scB[j];
                    float2 ceA = cepA[j * CC];

                    float qA0 = fmaf(a0.y, x0A, a0.x);
                    float qA1 = fmaf(a1.y, x0A, a1.x);
                    qA0 = fmaf(a0.z, x1A, qA0);
                    qA1 = fmaf(a1.z, x1A, qA1);
                    qA0 = fmaf(a0.w, xx0A, qA0);
                    qA1 = fmaf(a1.w, xx0A, qA1);
                    qA0 = fmaf(bbq.x, xx1A, qA0);
                    qA1 = fmaf(bbq.z, xx1A, qA1);
                    qA0 = fmaf(bbq.y, x01A, qA0);
                    qA1 = fmaf(bbq.w, x01A, qA1);

                    float pA0 = ex2f(qA0);
                    float pA1 = ex2f(qA1);
                    sA += pA0;
                    sA += pA1;
                    tA = fmaf(pA0, ceA.x, tA);
                    tA = fmaf(pA1, ceA.y, tA);
                }
            }
            if (actA) {
                spatial -= (double)(lg2f(sA) * LN2_F);
                efs     += (double)(tA / sA);
                cnt     += 1.0;
            }
        }
    }

    // ---- block reduce 4 doubles (uniform control, 4 warps) ----
    spatial = warpRedD(spatial);
    efs     = warpRedD(efs);
    cnt     = warpRedD(cnt);
    lam     = warpRedD(lam);
    const int wid = tid >> 5, lid = tid & 31;
    if (lid == 0) {
        red[wid]      = spatial;
        red[4 + wid]  = efs;
        red[8 + wid]  = cnt;
        red[12 + wid] = lam;
    }
    __syncthreads();
    if (tid == 0) {
        double s0 = 0, s1 = 0, s2 = 0, s3 = 0;
        #pragma unroll
        for (int w = 0; w < 4; w++) {
            s0 += red[w]; s1 += red[4 + w]; s2 += red[8 + w]; s3 += red[12 + w];
        }
        g_part[bid] = make_double4(s0, s1, s2, s3);
    }

    // ---- last-block-done finalize (deterministic fixed-order sum) ----
    __threadfence();
    if (tid == 0) {
        unsigned int v = atomicAdd(&g_done, 1u);
        isLast = (v == 2u * BB - 1u);
    }
    __syncthreads();
    if (isLast) {
        double lamSum = 0, cntSum = 0, l1Sum = 0, spSum = 0, efSum = 0;
        for (int b2 = tid; b2 < BB; b2 += TPB) {
            double4 e0 = g_part[2 * b2];
            double4 e1 = g_part[2 * b2 + 1];
            double sp = e0.x + e1.x;
            double ef = e0.y + e1.y;
            double gc = e0.z + e1.z;
            double lm = e0.w + e1.w;
            lamSum += lm;
            cntSum += gc;
            l1Sum  += fabs(lm - gc) * sqrt(gc + 1.0);
            spSum  += sp;
            efSum  += ef;
        }
        lamSum = warpRedD(lamSum);
        cntSum = warpRedD(cntSum);
        l1Sum  = warpRedD(l1Sum);
        spSum  = warpRedD(spSum);
        efSum  = warpRedD(efSum);
        __syncthreads();
        __shared__ double red5[4 * 5];
        if (lid == 0) {
            red5[wid]      = lamSum;
            red5[4 + wid]  = cntSum;
            red5[8 + wid]  = l1Sum;
            red5[12 + wid] = spSum;
            red5[16 + wid] = efSum;
        }
        __syncthreads();
        if (tid == 0) {
            double a0 = 0, a1 = 0, a2 = 0, a3 = 0, a4 = 0;
            #pragma unroll
            for (int w = 0; w < 4; w++) {
                a0 += red5[w]; a1 += red5[4 + w]; a2 += red5[8 + w];
                a3 += red5[12 + w]; a4 += red5[16 + w];
            }
            double count_loss = a0 / (double)BB;
            double n_total    = a1 > 1.0 ? a1 : 1.0;
            double count_l1   = a2 / (double)BB;
            double spatialL   = a3 / n_total;
            double efL        = a4 / n_total;
            double total = count_loss + spatialL + efL + count_l1;
            out[0] = (float)total;
            out[1] = (float)spatialL;
            out[2] = (float)count_loss;
            out[3] = (float)count_l1;
            out[4] = (float)efL;
            g_done = 0;  // reset for next graph replay
        }
    }
}

// ---------------- launch -------------------------------------------------------
extern "C" void kernel_launch(void* const* d_in, const int* in_sizes, int n_in,
                              void* d_out, int out_size) {
    const float* pi        = (const float*)d_in[0];
    const float* mu        = (const float*)d_in[1];
    const float* L         = (const float*)d_in[2];
    const float* ef_logits = (const float*)d_in[3];
    const float* tracks    = (const float*)d_in[4];
    const uint32_t* mask   = (const uint32_t*)d_in[5];

    main_kernel<<<2 * BB, TPB>>>(pi, mu, L, ef_logits, tracks, mask, (float*)d_out);
}